// round 11
// baseline (speedup 1.0000x reference)
#include <cuda_runtime.h>
#include <math.h>

#define NCTA 128
#define NTHREADS 1024
#define BB 256            // batch
#define SS 2048           // sequence
#define NIN 128
#define HH 256
#define NOUT 128
#define NG 8              // k-groups
#define KPG 32            // k per group

typedef unsigned long long ull;

// Persistent device state
__device__ __align__(16) float g_P[(size_t)SS * HH * BB];   // [t][j][b]
__device__ __align__(16) float g_h[2][HH * BB];             // [k][b], double buffered
__device__ int g_flags[NCTA];                               // monotonic per-CTA step flags

__device__ __forceinline__ float gelu_exact(float x) {
    return 0.5f * x * (1.0f + erff(x * 0.70710678118654752f));
}

// packed fp32x2 ops (sm_103a)
#define FMA2(acc, a, w) asm("fma.rn.f32x2 %0, %1, %2, %0;" : "+l"(acc) : "l"(a), "l"(w))
#define ADD2_(d, a, b)  asm("add.rn.f32x2 %0, %1, %2;"     : "=l"(d)  : "l"(a), "l"(b))
#define BARSYNC(id, n)  asm volatile("bar.sync %0, %1;" :: "r"(id), "r"(n) : "memory")

// ================= Precompute P[t][j][b] = sum_k X[b][t][k] * W_ih[j][k] + b_ih[j] =================
#define PCS 68
__global__ void __launch_bounds__(256, 1) precompute_P_kernel(
    const float* __restrict__ X, const float* __restrict__ W_ih,
    const float* __restrict__ b_ih)
{
    extern __shared__ float ps[];
    float* Ws = ps;
    float* Xs = ps + 128 * PCS;

    const int tid = threadIdx.x;
    const int b0 = blockIdx.x * 64;
    const int j0 = blockIdx.y * 64;
    const int t  = blockIdx.z;

    for (int e = tid; e < 64 * 128; e += 256) {
        int j = e >> 7, k = e & 127;
        Ws[k * PCS + j] = W_ih[(size_t)(j0 + j) * (NIN + HH) + k];
    }
    for (int e = tid; e < 64 * 128; e += 256) {
        int b = e >> 7, k = e & 127;
        Xs[k * PCS + b] = X[((size_t)(b0 + b) * SS + t) * NIN + k];
    }
    __syncthreads();

    const int tx = tid & 15;
    const int ty = tid >> 4;
    float acc[4][4];
    #pragma unroll
    for (int i = 0; i < 4; ++i)
        #pragma unroll
        for (int jj = 0; jj < 4; ++jj) acc[jj][i] = 0.f;

    #pragma unroll 8
    for (int k = 0; k < 128; ++k) {
        float4 wv = *(const float4*)&Ws[k * PCS + ty * 4];
        float4 xv = *(const float4*)&Xs[k * PCS + tx * 4];
        acc[0][0] = fmaf(wv.x, xv.x, acc[0][0]);
        acc[0][1] = fmaf(wv.x, xv.y, acc[0][1]);
        acc[0][2] = fmaf(wv.x, xv.z, acc[0][2]);
        acc[0][3] = fmaf(wv.x, xv.w, acc[0][3]);
        acc[1][0] = fmaf(wv.y, xv.x, acc[1][0]);
        acc[1][1] = fmaf(wv.y, xv.y, acc[1][1]);
        acc[1][2] = fmaf(wv.y, xv.z, acc[1][2]);
        acc[1][3] = fmaf(wv.y, xv.w, acc[1][3]);
        acc[2][0] = fmaf(wv.z, xv.x, acc[2][0]);
        acc[2][1] = fmaf(wv.z, xv.y, acc[2][1]);
        acc[2][2] = fmaf(wv.z, xv.z, acc[2][2]);
        acc[2][3] = fmaf(wv.z, xv.w, acc[2][3]);
        acc[3][0] = fmaf(wv.w, xv.x, acc[3][0]);
        acc[3][1] = fmaf(wv.w, xv.y, acc[3][1]);
        acc[3][2] = fmaf(wv.w, xv.z, acc[3][2]);
        acc[3][3] = fmaf(wv.w, xv.w, acc[3][3]);
    }

    #pragma unroll
    for (int jj = 0; jj < 4; ++jj) {
        int j = j0 + ty * 4 + jj;
        float bj = b_ih[j];
        float4 r = make_float4(acc[jj][0] + bj, acc[jj][1] + bj,
                               acc[jj][2] + bj, acc[jj][3] + bj);
        *(float4*)&g_P[((size_t)t * HH + j) * BB + b0 + tx * 4] = r;
    }
}

// ================= main persistent kernel =================
// 1024 threads = 8 k-groups x 128; thread (g, gt) owns batch pair {2gt,2gt+1},
// k in [32g, 32g+32). Sync: per-CTA release flags; group g waits only on its
// 16 producer CTAs' flags (fine-grained, no global barrier, no threadfence).
__global__ void __launch_bounds__(NTHREADS, 1) rec_kernel(
    const float* __restrict__ W_ih, const float* __restrict__ W_ho,
    const float* __restrict__ b_ho,
    const float* __restrict__ gamma, const float* __restrict__ beta,
    float* __restrict__ out)
{
    extern __shared__ __align__(16) ull dsm[];
    ull* sPZ0 = dsm;                     // [2][NG][128]
    ull* sPZ1 = dsm + 2 * NG * 128;
    ull* sPO  = dsm + 4 * NG * 128;
    __shared__ __align__(16) ull sW0d[HH];
    __shared__ __align__(16) ull sW1d[HH];
    __shared__ __align__(16) ull sWod[HH];
    __shared__ float sred[2][4][2];      // [group 0/1][warp][s,q]

    const int tid  = threadIdx.x;
    const int lane = tid & 31;
    const int g    = tid >> 7;      // k-group 0..7
    const int gt   = tid & 127;     // thread-in-group; owns b = 2gt, 2gt+1
    const int wg   = gt >> 5;       // warp within group
    const int c    = blockIdx.x;
    const int j0   = 2 * c;
    const int n0   = c;
    const int k0g  = g * KPG;

    // duplicated weight pairs {w,w}
    for (int k = tid; k < HH; k += NTHREADS) {
        unsigned w0 = __float_as_uint(W_ih[(size_t)j0 * (NIN + HH) + NIN + k]);
        unsigned w1 = __float_as_uint(W_ih[(size_t)(j0 + 1) * (NIN + HH) + NIN + k]);
        unsigned wo = __float_as_uint(W_ho[(size_t)n0 * HH + k]);
        sW0d[k] = ((ull)w0 << 32) | w0;
        sW1d[k] = ((ull)w1 << 32) | w1;
        sWod[k] = ((ull)wo << 32) | wo;
    }

    const float ga  = gamma[j0 + (g & 1)];
    const float be  = beta[j0 + (g & 1)];
    const float bho = b_ho[n0];

    const int base = __ldg(&g_flags[c]);   // uniform: all flags equal at launch
    __syncthreads();

    ull pPu = 0;
    if (g < 2)
        pPu = __ldg((const ull*)g_P + (size_t)(j0 + g) * 128 + gt);

    const int* myflag = &g_flags[(g << 4) + (lane & 15)];

    for (int t = 0; t <= SS; ++t) {
        // ===== wait for this group's 16 producer CTAs (trivial at t=0) =====
        {
            const int target = base + t;
            int v;
            do {
                asm volatile("ld.acquire.gpu.global.b32 %0, [%1];"
                             : "=r"(v) : "l"(myflag) : "memory");
            } while (__any_sync(0xffffffffu, v - target < 0));
        }

        const ull* __restrict__ hrow = (const ull*)(g_h[t & 1]);   // h_{t-1}, [256][128] pairs

        // ===== partial GEMMs over this group's 32 k (packed f32x2) =====
        ull z0 = 0ull, z1 = 0ull, oa = 0ull;
        #pragma unroll
        for (int kc = 0; kc < KPG; kc += 8) {
            ull a[8];
            #pragma unroll
            for (int i = 0; i < 8; ++i)
                a[i] = __ldcg(hrow + (size_t)(k0g + kc + i) * 128 + gt);
            #pragma unroll
            for (int i = 0; i < 8; i += 2) {
                const int k = k0g + kc + i;
                ulonglong2 w0 = *(const ulonglong2*)&sW0d[k];
                ulonglong2 w1 = *(const ulonglong2*)&sW1d[k];
                ulonglong2 wo = *(const ulonglong2*)&sWod[k];
                FMA2(z0, a[i],     w0.x);
                FMA2(z1, a[i],     w1.x);
                FMA2(oa, a[i],     wo.x);
                FMA2(z0, a[i + 1], w0.y);
                FMA2(z1, a[i + 1], w1.y);
                FMA2(oa, a[i + 1], wo.y);
            }
        }
        const int pb = (t & 1) * (NG * 128) + (g << 7) + gt;
        sPZ0[pb] = z0;
        sPZ1[pb] = z1;
        sPO [pb] = oa;
        __syncthreads();   // S1: all partials of step t visible

        // ===== group 2: o_{t-1} =====
        if (g == 2) {
            const ull* sp = sPO + (t & 1) * (NG * 128) + gt;
            ull p0 = sp[0],   p1 = sp[128], p2 = sp[256], p3 = sp[384];
            ull p4 = sp[512], p5 = sp[640], p6 = sp[768], p7 = sp[896];
            ull a01, a23, a45, a67, b03, b47, O;
            ADD2_(a01, p0, p1); ADD2_(a23, p2, p3);
            ADD2_(a45, p4, p5); ADD2_(a67, p6, p7);
            ADD2_(b03, a01, a23); ADD2_(b47, a45, a67);
            ADD2_(O, b03, b47);
            if (t > 0) {
                float2 of = *(float2*)&O;
                out[((size_t)(2 * gt)     * SS + (t - 1)) * NOUT + n0] = gelu_exact(of.x + bho);
                out[((size_t)(2 * gt + 1) * SS + (t - 1)) * NOUT + n0] = gelu_exact(of.y + bho);
            }
        }
        if (t == SS) break;

        // ===== groups 0/1: merge own z column + BN + GELU + h + flag =====
        if (g < 2) {
            const ull* sp = ((g == 0) ? sPZ0 : sPZ1) + (t & 1) * (NG * 128) + gt;
            ull p0 = sp[0],   p1 = sp[128], p2 = sp[256], p3 = sp[384];
            ull p4 = sp[512], p5 = sp[640], p6 = sp[768], p7 = sp[896];
            ull a01, a23, a45, a67, b03, b47, s8, Zm;
            ADD2_(a01, p0, p1); ADD2_(a23, p2, p3);
            ADD2_(a45, p4, p5); ADD2_(a67, p6, p7);
            ADD2_(b03, a01, a23); ADD2_(b47, a45, a67);
            ADD2_(s8, b03, b47);
            ADD2_(Zm, s8, pPu);
            float2 zf = *(float2*)&Zm;
            float zl = zf.x, zh = zf.y;

            float s = zl + zh;
            float q = fmaf(zl, zl, zh * zh);
            #pragma unroll
            for (int o = 16; o > 0; o >>= 1) {
                s += __shfl_down_sync(0xffffffffu, s, o);
                q += __shfl_down_sync(0xffffffffu, q, o);
            }
            if (lane == 0) { sred[g][wg][0] = s; sred[g][wg][1] = q; }
            BARSYNC(1 + g, 128);                       // group-scoped
            float S = sred[g][0][0] + sred[g][1][0] + sred[g][2][0] + sred[g][3][0];
            float Q = sred[g][0][1] + sred[g][1][1] + sred[g][2][1] + sred[g][3][1];
            float mu  = S * (1.0f / BB);
            float var = Q * (1.0f / BB) - mu * mu;     // biased
            float rs  = rsqrtf(var + 1e-5f);
            float h0 = gelu_exact((zl - mu) * rs * ga + be);
            float h1 = gelu_exact((zh - mu) * rs * ga + be);
            ((float2*)g_h[(t & 1) ^ 1])[(size_t)(j0 + g) * 128 + gt] = make_float2(h0, h1);

            BARSYNC(3, 256);                           // groups 0+1: h stores done
            if (tid == 0) {
                int nv = base + t + 1;
                asm volatile("st.release.gpu.global.b32 [%0], %1;"
                             :: "l"(&g_flags[c]), "r"(nv) : "memory");
            }
            if (t + 1 < SS)
                pPu = __ldg((const ull*)g_P + ((size_t)(t + 1) * HH + j0 + g) * 128 + gt);
        }
    }
}

// ---------------- launch ----------------
extern "C" void kernel_launch(void* const* d_in, const int* in_sizes, int n_in,
                              void* d_out, int out_size) {
    const float* X     = (const float*)d_in[0];
    const float* W_ih  = (const float*)d_in[1];
    const float* b_ih  = (const float*)d_in[2];
    const float* W_ho  = (const float*)d_in[3];
    const float* b_ho  = (const float*)d_in[4];
    const float* gamma = (const float*)d_in[5];
    const float* beta  = (const float*)d_in[6];
    float* out = (float*)d_out;

    // zero h buffer 0 (h_{-1} = 0)
    void* hptr = nullptr;
    cudaGetSymbolAddress(&hptr, g_h);
    cudaMemsetAsync(hptr, 0, sizeof(float) * HH * BB, 0);

    // precompute P = X @ Wx.T + b_ih
    {
        size_t psmem = 2u * 128 * PCS * sizeof(float);
        cudaFuncSetAttribute(precompute_P_kernel,
                             cudaFuncAttributeMaxDynamicSharedMemorySize, (int)psmem);
        dim3 pgrid(4, 4, SS);
        precompute_P_kernel<<<pgrid, 256, psmem>>>(X, W_ih, b_ih);
    }

    // persistent recurrence kernel
    const size_t dsm_bytes = 6u * NG * 128 * sizeof(ull);   // 48KB partial buffers
    cudaFuncSetAttribute(rec_kernel, cudaFuncAttributeMaxDynamicSharedMemorySize,
                         (int)dsm_bytes);
    rec_kernel<<<NCTA, NTHREADS, dsm_bytes>>>(W_ih, W_ho, b_ho, gamma, beta, out);
}

// round 12
// speedup vs baseline: 3.0358x; 3.0358x over previous
#include <cuda_runtime.h>
#include <math.h>

#define NCTA 128
#define NTHREADS 1024
#define BB 256            // batch
#define SS 2048           // sequence
#define NIN 128
#define HH 256
#define NOUT 128
#define NG 8              // k-groups
#define KPG 32            // k per group

typedef unsigned long long ull;

// Persistent device state
__device__ __align__(16) float g_P[(size_t)SS * HH * BB];   // [t][j][b]
__device__ __align__(16) float g_h[2][HH * BB];             // [k][b], double buffered
__device__ unsigned g_ctr;                                  // monotonic arrival counter

__device__ __forceinline__ float gelu_exact(float x) {
    return 0.5f * x * (1.0f + erff(x * 0.70710678118654752f));
}

// packed fp32x2 ops (sm_103a)
#define FMA2(acc, a, w) asm("fma.rn.f32x2 %0, %1, %2, %0;" : "+l"(acc) : "l"(a), "l"(w))
#define ADD2_(d, a, b)  asm("add.rn.f32x2 %0, %1, %2;"     : "=l"(d)  : "l"(a), "l"(b))
#define BARSYNC(id, n)  asm volatile("bar.sync %0, %1;" :: "r"(id), "r"(n) : "memory")

// ================= Precompute P[t][j][b] = sum_k X[b][t][k] * W_ih[j][k] + b_ih[j] =================
#define PCS 68
__global__ void __launch_bounds__(256, 1) precompute_P_kernel(
    const float* __restrict__ X, const float* __restrict__ W_ih,
    const float* __restrict__ b_ih)
{
    extern __shared__ float ps[];
    float* Ws = ps;
    float* Xs = ps + 128 * PCS;

    const int tid = threadIdx.x;
    const int b0 = blockIdx.x * 64;
    const int j0 = blockIdx.y * 64;
    const int t  = blockIdx.z;

    for (int e = tid; e < 64 * 128; e += 256) {
        int j = e >> 7, k = e & 127;
        Ws[k * PCS + j] = W_ih[(size_t)(j0 + j) * (NIN + HH) + k];
    }
    for (int e = tid; e < 64 * 128; e += 256) {
        int b = e >> 7, k = e & 127;
        Xs[k * PCS + b] = X[((size_t)(b0 + b) * SS + t) * NIN + k];
    }
    __syncthreads();

    const int tx = tid & 15;
    const int ty = tid >> 4;
    float acc[4][4];
    #pragma unroll
    for (int i = 0; i < 4; ++i)
        #pragma unroll
        for (int jj = 0; jj < 4; ++jj) acc[jj][i] = 0.f;

    #pragma unroll 8
    for (int k = 0; k < 128; ++k) {
        float4 wv = *(const float4*)&Ws[k * PCS + ty * 4];
        float4 xv = *(const float4*)&Xs[k * PCS + tx * 4];
        acc[0][0] = fmaf(wv.x, xv.x, acc[0][0]);
        acc[0][1] = fmaf(wv.x, xv.y, acc[0][1]);
        acc[0][2] = fmaf(wv.x, xv.z, acc[0][2]);
        acc[0][3] = fmaf(wv.x, xv.w, acc[0][3]);
        acc[1][0] = fmaf(wv.y, xv.x, acc[1][0]);
        acc[1][1] = fmaf(wv.y, xv.y, acc[1][1]);
        acc[1][2] = fmaf(wv.y, xv.z, acc[1][2]);
        acc[1][3] = fmaf(wv.y, xv.w, acc[1][3]);
        acc[2][0] = fmaf(wv.z, xv.x, acc[2][0]);
        acc[2][1] = fmaf(wv.z, xv.y, acc[2][1]);
        acc[2][2] = fmaf(wv.z, xv.z, acc[2][2]);
        acc[2][3] = fmaf(wv.z, xv.w, acc[2][3]);
        acc[3][0] = fmaf(wv.w, xv.x, acc[3][0]);
        acc[3][1] = fmaf(wv.w, xv.y, acc[3][1]);
        acc[3][2] = fmaf(wv.w, xv.z, acc[3][2]);
        acc[3][3] = fmaf(wv.w, xv.w, acc[3][3]);
    }

    #pragma unroll
    for (int jj = 0; jj < 4; ++jj) {
        int j = j0 + ty * 4 + jj;
        float bj = b_ih[j];
        float4 r = make_float4(acc[jj][0] + bj, acc[jj][1] + bj,
                               acc[jj][2] + bj, acc[jj][3] + bj);
        *(float4*)&g_P[((size_t)t * HH + j) * BB + b0 + tx * 4] = r;
    }
}

// ================= main persistent kernel =================
// 1024 threads = 8 k-groups x 128; thread (g, gt) owns batch pair {2gt,2gt+1},
// k in [32g, 32g+32), packed f32x2 math. Central barrier = single monotonic
// counter: red.release arrival (after groups 0/1's h stores), tid0 acquire-spin.
// Tail: group 0 -> BN column j0, group 1 -> j0+1, group 2 -> output column.
__global__ void __launch_bounds__(NTHREADS, 1) rec_kernel(
    const float* __restrict__ W_ih, const float* __restrict__ W_ho,
    const float* __restrict__ b_ho,
    const float* __restrict__ gamma, const float* __restrict__ beta,
    float* __restrict__ out)
{
    __shared__ __align__(16) ull sPZ0[NG * 128];   // per-group partials
    __shared__ __align__(16) ull sPZ1[NG * 128];
    __shared__ __align__(16) ull sPO [NG * 128];
    __shared__ __align__(16) ull sW0d[HH];         // {w,w} duplicated pairs
    __shared__ __align__(16) ull sW1d[HH];
    __shared__ __align__(16) ull sWod[HH];
    __shared__ float sred[2][4][2];                // [group 0/1][warp][s,q]
    __shared__ unsigned s_base;

    const int tid  = threadIdx.x;
    const int lane = tid & 31;
    const int g    = tid >> 7;      // k-group 0..7
    const int gt   = tid & 127;     // thread-in-group; owns b = 2gt, 2gt+1
    const int wg   = gt >> 5;       // warp within group
    const int c    = blockIdx.x;
    const int j0   = 2 * c;
    const int n0   = c;
    const int k0g  = g * KPG;

    // duplicated weight pairs {w,w}
    for (int k = tid; k < HH; k += NTHREADS) {
        unsigned w0 = __float_as_uint(W_ih[(size_t)j0 * (NIN + HH) + NIN + k]);
        unsigned w1 = __float_as_uint(W_ih[(size_t)(j0 + 1) * (NIN + HH) + NIN + k]);
        unsigned wo = __float_as_uint(W_ho[(size_t)n0 * HH + k]);
        sW0d[k] = ((ull)w0 << 32) | w0;
        sW1d[k] = ((ull)w1 << 32) | w1;
        sWod[k] = ((ull)wo << 32) | wo;
    }

    const float ga  = gamma[j0 + (g & 1)];
    const float be  = beta[j0 + (g & 1)];
    const float bho = b_ho[n0];

    if (tid == 0) {
        unsigned v;
        asm volatile("ld.acquire.gpu.global.b32 %0, [%1];" : "=r"(v) : "l"(&g_ctr));
        s_base = v;                     // counter value at launch (same for all CTAs)
    }
    __syncthreads();
    const unsigned base = s_base;

    ull pPu = 0;
    if (g < 2)
        pPu = __ldg((const ull*)g_P + (size_t)(j0 + g) * 128 + gt);

    for (int t = 0; t <= SS; ++t) {
        const ull* __restrict__ hrow = (const ull*)(g_h[t & 1]);   // h_{t-1}, [256][128] pairs

        // ===== partial GEMMs over this group's 32 k (packed f32x2) =====
        ull z0 = 0ull, z1 = 0ull, oa = 0ull;
        #pragma unroll
        for (int kc = 0; kc < KPG; kc += 8) {
            ull a[8];
            #pragma unroll
            for (int i = 0; i < 8; ++i)
                a[i] = __ldcg(hrow + (size_t)(k0g + kc + i) * 128 + gt);
            #pragma unroll
            for (int i = 0; i < 8; i += 2) {
                const int k = k0g + kc + i;
                ulonglong2 w0 = *(const ulonglong2*)&sW0d[k];
                ulonglong2 w1 = *(const ulonglong2*)&sW1d[k];
                ulonglong2 wo = *(const ulonglong2*)&sWod[k];
                FMA2(z0, a[i],     w0.x);
                FMA2(z1, a[i],     w1.x);
                FMA2(oa, a[i],     wo.x);
                FMA2(z0, a[i + 1], w0.y);
                FMA2(z1, a[i + 1], w1.y);
                FMA2(oa, a[i + 1], wo.y);
            }
        }
        const int pb = (g << 7) + gt;
        sPZ0[pb] = z0;
        sPZ1[pb] = z1;
        sPO [pb] = oa;
        __syncthreads();   // S1: partials of step t visible; everyone done reading h_{t-1}

        // ===== group 2: o_{t-1} (tree merge; off the release path) =====
        if (g == 2 && t > 0) {
            const ull* sp = sPO + gt;
            ull a01, a23, a45, a67, b03, b47, O;
            ADD2_(a01, sp[0],   sp[128]); ADD2_(a23, sp[256], sp[384]);
            ADD2_(a45, sp[512], sp[640]); ADD2_(a67, sp[768], sp[896]);
            ADD2_(b03, a01, a23); ADD2_(b47, a45, a67);
            ADD2_(O, b03, b47);
            float2 of = *(float2*)&O;
            out[((size_t)(2 * gt)     * SS + (t - 1)) * NOUT + n0] = gelu_exact(of.x + bho);
            out[((size_t)(2 * gt + 1) * SS + (t - 1)) * NOUT + n0] = gelu_exact(of.y + bho);
        }
        if (t == SS) break;

        // ===== groups 0/1: merge own z column + BN + GELU + h store + arrival =====
        if (g < 2) {
            const ull* sp = ((g == 0) ? sPZ0 : sPZ1) + gt;
            ull a01, a23, a45, a67, b03, b47, s8, Zm;
            ADD2_(a01, sp[0],   sp[128]); ADD2_(a23, sp[256], sp[384]);
            ADD2_(a45, sp[512], sp[640]); ADD2_(a67, sp[768], sp[896]);
            ADD2_(b03, a01, a23); ADD2_(b47, a45, a67);
            ADD2_(s8, b03, b47);
            ADD2_(Zm, s8, pPu);
            float2 zf = *(float2*)&Zm;
            float zl = zf.x, zh = zf.y;

            float s = zl + zh;
            float q = fmaf(zl, zl, zh * zh);
            #pragma unroll
            for (int o = 16; o > 0; o >>= 1) {
                s += __shfl_down_sync(0xffffffffu, s, o);
                q += __shfl_down_sync(0xffffffffu, q, o);
            }
            if (lane == 0) { sred[g][wg][0] = s; sred[g][wg][1] = q; }
            BARSYNC(1 + g, 128);                       // group-scoped reduce
            float S = sred[g][0][0] + sred[g][1][0] + sred[g][2][0] + sred[g][3][0];
            float Q = sred[g][0][1] + sred[g][1][1] + sred[g][2][1] + sred[g][3][1];
            float mu  = S * (1.0f / BB);
            float var = Q * (1.0f / BB) - mu * mu;     // biased
            float rs  = rsqrtf(var + 1e-5f);
            float h0 = gelu_exact((zl - mu) * rs * ga + be);
            float h1 = gelu_exact((zh - mu) * rs * ga + be);
            ((float2*)g_h[(t & 1) ^ 1])[(size_t)(j0 + g) * 128 + gt] = make_float2(h0, h1);

            BARSYNC(3, 256);                           // groups 0+1: h stores issued
            if (tid == 0)                              // arrival (release orders h stores)
                asm volatile("red.release.gpu.global.add.u32 [%0], %1;"
                             :: "l"(&g_ctr), "r"(1u) : "memory");
            if (t + 1 < SS)                            // prefetch next P off the path
                pPu = __ldg((const ull*)g_P + ((size_t)(t + 1) * HH + j0 + g) * 128 + gt);
        }

        // ===== wait: all 128 CTAs arrived for step t =====
        if (tid == 0) {
            const unsigned target = base + (unsigned)(t + 1) * NCTA;
            unsigned v;
            do {
                asm volatile("ld.acquire.gpu.global.b32 %0, [%1];"
                             : "=r"(v) : "l"(&g_ctr) : "memory");
            } while ((int)(v - target) < 0);
        }
        __syncthreads();   // S4: barrier passed; safe to read h_t and overwrite partials
    }
}

// ---------------- launch ----------------
extern "C" void kernel_launch(void* const* d_in, const int* in_sizes, int n_in,
                              void* d_out, int out_size) {
    const float* X     = (const float*)d_in[0];
    const float* W_ih  = (const float*)d_in[1];
    const float* b_ih  = (const float*)d_in[2];
    const float* W_ho  = (const float*)d_in[3];
    const float* b_ho  = (const float*)d_in[4];
    const float* gamma = (const float*)d_in[5];
    const float* beta  = (const float*)d_in[6];
    float* out = (float*)d_out;

    // zero h buffer 0 (h_{-1} = 0)
    void* hptr = nullptr;
    cudaGetSymbolAddress(&hptr, g_h);
    cudaMemsetAsync(hptr, 0, sizeof(float) * HH * BB, 0);

    // precompute P = X @ Wx.T + b_ih
    {
        size_t psmem = 2u * 128 * PCS * sizeof(float);
        cudaFuncSetAttribute(precompute_P_kernel,
                             cudaFuncAttributeMaxDynamicSharedMemorySize, (int)psmem);
        dim3 pgrid(4, 4, SS);
        precompute_P_kernel<<<pgrid, 256, psmem>>>(X, W_ih, b_ih);
    }

    // persistent recurrence kernel (static smem only)
    rec_kernel<<<NCTA, NTHREADS>>>(W_ih, W_ho, b_ho, gamma, beta, out);
}